// round 14
// baseline (speedup 1.0000x reference)
#include <cuda_runtime.h>
#include <cuda_fp16.h>
#include <cstdint>

#define CM 1024
#define TT 2048
#define BB 4
#define HH 16
#define MR (BB*TT)   // 8192 rows

// ---------------------------------------------------------------------------
// Scratch (device globals: allocation-free per harness rules). fp16.
// ---------------------------------------------------------------------------
__device__ __half g_x_hi[(size_t)MR * CM];
__device__ __half g_wqkv_hi[3 * CM * CM];
__device__ __half g_wout_hi[CM * CM];
__device__ __half g_qkv_hi[(size_t)MR * 3 * CM];
__device__ __half g_att_hi[(size_t)MR * CM];

// ---------------------------------------------------------------------------
// helpers
// ---------------------------------------------------------------------------
__device__ __forceinline__ uint32_t smem_u32(const void* p) {
  uint32_t a;
  asm("{ .reg .u64 t; cvta.to.shared.u64 t, %1; cvt.u32.u64 %0, t; }"
      : "=r"(a) : "l"(p));
  return a;
}
__device__ __forceinline__ void cp16(uint32_t s, const void* g) {
  asm volatile("cp.async.cg.shared.global [%0], [%1], 16;" :: "r"(s), "l"(g));
}
#define CP_COMMIT() asm volatile("cp.async.commit_group;" ::: "memory")
#define CP_WAIT(n)  asm volatile("cp.async.wait_group %0;" :: "n"(n) : "memory")

// D += A*B, m16n8k16 fp16 operands, fp32 accumulate
__device__ __forceinline__ void mma16(float* d, uint32_t a0, uint32_t a1,
                                      uint32_t a2, uint32_t a3,
                                      uint32_t b0, uint32_t b1) {
  asm volatile(
      "mma.sync.aligned.m16n8k16.row.col.f32.f16.f16.f32 "
      "{%0,%1,%2,%3}, {%4,%5,%6,%7}, {%8,%9}, {%0,%1,%2,%3};"
      : "+f"(d[0]), "+f"(d[1]), "+f"(d[2]), "+f"(d[3])
      : "r"(a0), "r"(a1), "r"(a2), "r"(a3), "r"(b0), "r"(b1));
}
__device__ __forceinline__ void ldsm4t(uint32_t& r0, uint32_t& r1,
                                       uint32_t& r2, uint32_t& r3, uint32_t a) {
  asm volatile("ldmatrix.sync.aligned.m8n8.x4.trans.shared.b16 "
               "{%0,%1,%2,%3}, [%4];"
               : "=r"(r0), "=r"(r1), "=r"(r2), "=r"(r3) : "r"(a));
}
__device__ __forceinline__ uint32_t ldu(const void* p) {
  return *(const uint32_t*)p;
}
__device__ __forceinline__ uint32_t sw128(uint32_t o) { return o ^ ((o >> 3) & 0x70); }

__device__ __forceinline__ uint32_t pack_h2(float a, float b) {
  __half2 p = __floats2half2_rn(a, b);
  return *(uint32_t*)&p;
}

// ---------------------------------------------------------------------------
// single fused cast kernel: all three fp32 inputs -> fp16
// ---------------------------------------------------------------------------
#define NX (MR * CM / 4)
#define NW (3 * CM * CM / 4)
#define NO (CM * CM / 4)

__global__ __launch_bounds__(256) void cast_all(
    const float* __restrict__ x, const float* __restrict__ wq,
    const float* __restrict__ wo,
    __half* __restrict__ xh, __half* __restrict__ wqh,
    __half* __restrict__ woh) {
  int i = blockIdx.x * blockDim.x + threadIdx.x;
  const float* src;
  __half* dst;
  int j;
  if (i < NX)            { src = x;  dst = xh;  j = i; }
  else if (i < NX + NW)  { src = wq; dst = wqh; j = i - NX; }
  else if (i < NX + NW + NO) { src = wo; dst = woh; j = i - NX - NW; }
  else return;
  float4 v = ((const float4*)src)[j];
  ((uint2*)dst)[j] = make_uint2(pack_h2(v.x, v.y), pack_h2(v.z, v.w));
}

// ---------------------------------------------------------------------------
// fp16 TN GEMM: C[M,N] = Ah[M,K] * Bh[N,K]^T, fp32 accumulate.
// CTA 128x128, BK=64, 4 SMEM stages / 3 in flight -> SINGLE sync per iter
// (block c+3 lands in stage (c+3)%4 = slot freed at c-1; fill issues before
// the MMA burst so cp.async latency hides under tensor work).
// MODE 0: write fp32 C.  MODE 1: write fp16 C.
// ---------------------------------------------------------------------------
#define GSTAGE 32768                    // Ah 16K | Bh 16K
#define GSMEM_TOTAL (4 * GSTAGE)        // 128 KB

template<int MODE>
__global__ __launch_bounds__(256) void gemmH(
    const __half* __restrict__ Ah_, const __half* __restrict__ Bh_,
    float* __restrict__ Cf, __half* __restrict__ Ch, int N, int K) {
  extern __shared__ char sm[];
  const int tid = threadIdx.x, w = tid >> 5, lane = tid & 31;
  const int g = lane >> 2, t = lane & 3;
  const int wm = w & 1, wn = w >> 1;
  const int bm = blockIdx.y * 128, bn = blockIdx.x * 128;

  float acc[4][4][4];
#pragma unroll
  for (int mt = 0; mt < 4; mt++)
#pragma unroll
    for (int nt = 0; nt < 4; nt++)
#pragma unroll
      for (int r = 0; r < 4; r++) acc[mt][nt][r] = 0.f;

  auto fill = [&](int s, int k0) {
    char* base = sm + s * GSTAGE;
#pragma unroll
    for (int i = tid; i < 2048; i += 256) {
      int buf = i >> 10;            // 0=Ah, 1=Bh
      int row = (i >> 3) & 127;
      int c = i & 7;
      uint32_t swo = sw128((uint32_t)(row * 128 + c * 16));
      size_t off = (size_t)((buf ? bn : bm) + row) * K + k0 + c * 8;
      cp16(smem_u32(base + buf * 16384 + swo), (buf ? Bh_ : Ah_) + off);
    }
  };

  const int KT = K >> 6;
  fill(0, 0);   CP_COMMIT();
  fill(1, 64);  CP_COMMIT();
  fill(2, 128); CP_COMMIT();

  const uint32_t xg = (uint32_t)g << 4;

  for (int c = 0; c < KT; c++) {
    const int s = c & 3;
    CP_WAIT(2);            // stage c's group complete (3 groups outstanding max)
    __syncthreads();       // all warps done reading stage (c-1)&3 -> free slot
    if (c + 3 < KT) fill((c + 3) & 3, (c + 3) * 64);
    CP_COMMIT();

    const char* Ah = sm + s * GSTAGE;
    const char* Bh = Ah + 16384;

    uint32_t ah[2][4][4], bh[2][4][2];

    auto loadFrags = [&](int kt, int buf) {
      const uint32_t xo = ((uint32_t)(kt * 32 + t * 4)) ^ xg;
#pragma unroll
      for (int mt = 0; mt < 4; mt++) {
        const char* ar = Ah + (wm * 64 + mt * 16 + g) * 128;
        ah[buf][mt][0] = ldu(ar + xo);
        ah[buf][mt][1] = ldu(ar + 1024 + xo);
        ah[buf][mt][2] = ldu(ar + (xo ^ 16));
        ah[buf][mt][3] = ldu(ar + 1024 + (xo ^ 16));
      }
#pragma unroll
      for (int nt = 0; nt < 4; nt++) {
        const char* br = Bh + (wn * 32 + nt * 8 + g) * 128;
        bh[buf][nt][0] = ldu(br + xo);
        bh[buf][nt][1] = ldu(br + (xo ^ 16));
      }
    };

    loadFrags(0, 0);
#pragma unroll
    for (int kt = 0; kt < 4; kt++) {
      const int cur = kt & 1;
      if (kt < 3) loadFrags(kt + 1, cur ^ 1);
#pragma unroll
      for (int nt = 0; nt < 4; nt++)
#pragma unroll
        for (int mt = 0; mt < 4; mt++)
          mma16(acc[mt][nt], ah[cur][mt][0], ah[cur][mt][1],
                ah[cur][mt][2], ah[cur][mt][3], bh[cur][nt][0], bh[cur][nt][1]);
    }
  }

#pragma unroll
  for (int mt = 0; mt < 4; mt++) {
#pragma unroll
    for (int nt = 0; nt < 4; nt++) {
      const int row = bm + wm * 64 + mt * 16 + g;
      const int col = bn + wn * 32 + nt * 8 + 2 * t;
      if (MODE == 0) {
        *(float2*)(Cf + (size_t)row * N + col) =
            make_float2(acc[mt][nt][0], acc[mt][nt][1]);
        *(float2*)(Cf + (size_t)(row + 8) * N + col) =
            make_float2(acc[mt][nt][2], acc[mt][nt][3]);
      } else {
        *(uint32_t*)(Ch + (size_t)row * N + col) =
            pack_h2(acc[mt][nt][0], acc[mt][nt][1]);
        *(uint32_t*)(Ch + (size_t)(row + 8) * N + col) =
            pack_h2(acc[mt][nt][2], acc[mt][nt][3]);
      }
    }
  }
}

// ---------------------------------------------------------------------------
// fp16 causal flash attention, TQ=128, 8 warps (2 warps/SMSP for latency
// cover), one m16 tile per warp. S = Qh*Kh^T ; O += Ph*Vh.
// SMEM: Qh 16K | Kh x2 16K | Vh x2 16K = 48KB -> 2 CTAs/SM.
// ---------------------------------------------------------------------------
#define TQ 128
#define AQH 0
#define AKH 16384
#define AVH 32768
#define ASMEM_TOTAL 49152

__global__ __launch_bounds__(256) void attn1(
    const __half* __restrict__ qh, __half* __restrict__ oh) {
  extern __shared__ char sm[];
  const int qi = blockIdx.x, h = blockIdx.y, b = blockIdx.z;
  const int tid = threadIdx.x, w = tid >> 5, lane = tid & 31;
  const int g = lane >> 2, t = lane & 3;
  const int q0 = qi * TQ;
  const int r0 = w * 16 + g;                 // local q row (r1 = r0+8)
  const size_t rowQ = (size_t)(b * TT + q0);

  auto fillKV = [&](int kb, int bf) {
    const size_t base = (size_t)(b * TT + kb * 64) * 3 * CM + CM + h * 64;
    char* kh = sm + AKH + bf * 8192;
    char* vh = sm + AVH + bf * 8192;
#pragma unroll
    for (int i = tid; i < 512; i += 256) {
      int row = i >> 3, c = i & 7;
      uint32_t swo = sw128((uint32_t)(row * 128 + c * 16));
      size_t src = base + (size_t)row * 3 * CM + c * 8;
      cp16(smem_u32(kh + swo), qh + src);
      cp16(smem_u32(vh + swo), qh + src + CM);
    }
  };

  // prologue: Qh (128 rows) + KV block 0
#pragma unroll
  for (int i = tid; i < 1024; i += 256) {
    int row = i >> 3, c = i & 7;
    uint32_t swo = sw128((uint32_t)(row * 128 + c * 16));
    size_t src = (rowQ + row) * 3 * CM + h * 64 + c * 8;
    cp16(smem_u32(sm + AQH + swo), qh + src);
  }
  fillKV(0, 0);
  CP_COMMIT();

  float m0 = -1e30f, m1 = -1e30f, l0 = 0.f, l1 = 0.f;
  float o[8][4];
#pragma unroll
  for (int j = 0; j < 8; j++)
#pragma unroll
    for (int r = 0; r < 4; r++) o[j][r] = 0.f;

  const uint32_t xg = (uint32_t)g << 4;
  const int KJ = 2 * qi + 2;                 // key blocks 0 .. 2qi+1

  for (int kj = 0; kj < KJ; kj++) {
    const int buf = kj & 1;
    if (kj + 1 < KJ) fillKV(kj + 1, buf ^ 1);
    CP_COMMIT();
    CP_WAIT(1);
    __syncthreads();

    const char* Kh = sm + AKH + buf * 8192;
    const char* Qh = sm + AQH;
    const uint32_t vhU = smem_u32(sm + AVH + buf * 8192);

    // ---- S = Qh Kh^T (1-pass) ----
    float s[8][4];
#pragma unroll
    for (int j = 0; j < 8; j++)
#pragma unroll
      for (int r = 0; r < 4; r++) s[j][r] = 0.f;

#pragma unroll
    for (int kt = 0; kt < 4; kt++) {
      const uint32_t xo = ((uint32_t)(kt * 32 + t * 4)) ^ xg;
      const char* qrh = Qh + r0 * 128;
      uint32_t ah0 = ldu(qrh + xo),        ah1 = ldu(qrh + 1024 + xo);
      uint32_t ah2 = ldu(qrh + (xo ^ 16)), ah3 = ldu(qrh + 1024 + (xo ^ 16));
#pragma unroll
      for (int j = 0; j < 8; j++) {
        const char* krh = Kh + (j * 8 + g) * 128;
        uint32_t bh0 = ldu(krh + xo), bh1 = ldu(krh + (xo ^ 16));
        mma16(s[j], ah0, ah1, ah2, ah3, bh0, bh1);
      }
    }

    // scale 1/sqrt(64), causal mask (global-index compare, near diag only)
#pragma unroll
    for (int j = 0; j < 8; j++)
#pragma unroll
      for (int r = 0; r < 4; r++) s[j][r] *= 0.125f;

    if (kj >= 2 * qi) {
      const int colb = kj * 64;
      const int rg = q0 + r0;
#pragma unroll
      for (int j = 0; j < 8; j++) {
        const int c = colb + j * 8 + 2 * t;
        if (c     > rg)     s[j][0] = -1e30f;
        if (c + 1 > rg)     s[j][1] = -1e30f;
        if (c     > rg + 8) s[j][2] = -1e30f;
        if (c + 1 > rg + 8) s[j][3] = -1e30f;
      }
    }

    // ---- online softmax (rows r0, r0+8; 4 quad lanes share a row) ----
    float rm0 = -1e30f, rm1 = -1e30f;
#pragma unroll
    for (int j = 0; j < 8; j++) {
      rm0 = fmaxf(rm0, fmaxf(s[j][0], s[j][1]));
      rm1 = fmaxf(rm1, fmaxf(s[j][2], s[j][3]));
    }
    rm0 = fmaxf(rm0, __shfl_xor_sync(0xffffffffu, rm0, 1));
    rm0 = fmaxf(rm0, __shfl_xor_sync(0xffffffffu, rm0, 2));
    rm1 = fmaxf(rm1, __shfl_xor_sync(0xffffffffu, rm1, 1));
    rm1 = fmaxf(rm1, __shfl_xor_sync(0xffffffffu, rm1, 2));
    const float mn0 = fmaxf(m0, rm0), mn1 = fmaxf(m1, rm1);
    const float al_0 = __expf(m0 - mn0), al_1 = __expf(m1 - mn1);
    float rs0 = 0.f, rs1 = 0.f;
#pragma unroll
    for (int j = 0; j < 8; j++) {
      s[j][0] = __expf(s[j][0] - mn0);
      s[j][1] = __expf(s[j][1] - mn0);
      s[j][2] = __expf(s[j][2] - mn1);
      s[j][3] = __expf(s[j][3] - mn1);
      rs0 += s[j][0] + s[j][1];
      rs1 += s[j][2] + s[j][3];
    }
    rs0 += __shfl_xor_sync(0xffffffffu, rs0, 1);
    rs0 += __shfl_xor_sync(0xffffffffu, rs0, 2);
    rs1 += __shfl_xor_sync(0xffffffffu, rs1, 1);
    rs1 += __shfl_xor_sync(0xffffffffu, rs1, 2);
    l0 = l0 * al_0 + rs0;  m0 = mn0;
    l1 = l1 * al_1 + rs1;  m1 = mn1;
#pragma unroll
    for (int j = 0; j < 8; j++) {
      o[j][0] *= al_0; o[j][1] *= al_0;
      o[j][2] *= al_1; o[j][3] *= al_1;
    }

    // ---- P -> fp16, in registers (acc layout == A-frag layout) ----
    uint32_t ph01[8], ph23[8];
#pragma unroll
    for (int j = 0; j < 8; j++) {
      ph01[j] = pack_h2(s[j][0], s[j][1]);
      ph23[j] = pack_h2(s[j][2], s[j][3]);
    }

    // ---- O += Ph Vh (V^T via ldmatrix.x4.trans) ----
    const int qq = lane >> 3, rr = lane & 7;
#pragma unroll
    for (int kt = 0; kt < 4; kt++) {
      const uint32_t pa0 = ph01[2*kt],   pa1 = ph23[2*kt];
      const uint32_t pa2 = ph01[2*kt+1], pa3 = ph23[2*kt+1];
      const uint32_t vrow = (uint32_t)(kt * 16 + ((qq & 1) << 3) + rr);
#pragma unroll
      for (int jp = 0; jp < 4; jp++) {
        const uint32_t off = sw128(vrow * 128 + (uint32_t)(jp * 32 + ((qq >> 1) << 4)));
        uint32_t vh0, vh1, vh2, vh3;
        ldsm4t(vh0, vh1, vh2, vh3, vhU + off);
        mma16(o[2*jp],     pa0, pa1, pa2, pa3, vh0, vh1);
        mma16(o[2*jp + 1], pa0, pa1, pa2, pa3, vh2, vh3);
      }
    }
    __syncthreads();   // tiles consumed before next prefetch overwrites
  }

  // ---- epilogue: O /= l, fp16 ----
  const float i0 = 1.f / l0, i1 = 1.f / l1;
  const size_t ro0 = (rowQ + r0) * CM + h * 64;
  const size_t ro1 = ro0 + 8 * (size_t)CM;
#pragma unroll
  for (int j = 0; j < 8; j++) {
    const int col = j * 8 + 2 * t;
    *(uint32_t*)(oh + ro0 + col) = pack_h2(o[j][0] * i0, o[j][1] * i0);
    *(uint32_t*)(oh + ro1 + col) = pack_h2(o[j][2] * i1, o[j][3] * i1);
  }
}

// ---------------------------------------------------------------------------
extern "C" void kernel_launch(void* const* d_in, const int* in_sizes, int n_in,
                              void* d_out, int out_size) {
  const float* x     = (const float*)d_in[0];   // [4,2048,1024]
  const float* w_qkv = (const float*)d_in[1];   // [3072,1024]
  const float* w_out = (const float*)d_in[2];   // [1024,1024]
  float* out = (float*)d_out;

  __half *xh, *wqh, *woh, *qkvh, *ath;
  cudaGetSymbolAddress((void**)&xh,  g_x_hi);
  cudaGetSymbolAddress((void**)&wqh, g_wqkv_hi);
  cudaGetSymbolAddress((void**)&woh, g_wout_hi);
  cudaGetSymbolAddress((void**)&qkvh, g_qkv_hi);
  cudaGetSymbolAddress((void**)&ath, g_att_hi);

  cudaFuncSetAttribute(gemmH<1>, cudaFuncAttributeMaxDynamicSharedMemorySize, GSMEM_TOTAL);
  cudaFuncSetAttribute(gemmH<0>, cudaFuncAttributeMaxDynamicSharedMemorySize, GSMEM_TOTAL);
  cudaFuncSetAttribute(attn1,    cudaFuncAttributeMaxDynamicSharedMemorySize, ASMEM_TOTAL);

  // 0) cast all inputs to fp16 (single launch)
  cast_all<<<(NX + NW + NO + 255) / 256, 256>>>(x, w_qkv, w_out, xh, wqh, woh);

  // 1) QKV projection -> qkv fp16 (1-pass)
  gemmH<1><<<dim3(3*CM/128, MR/128), 256, GSMEM_TOTAL>>>(
      xh, wqh, nullptr, qkvh, 3*CM, CM);

  // 2) causal flash attention -> att fp16 (TQ=128, 8 warps)
  attn1<<<dim3(TT/TQ, HH, BB), 256, ASMEM_TOTAL>>>(qkvh, ath);

  // 3) output projection -> fp32 out (1-pass)
  gemmH<0><<<dim3(CM/128, MR/128), 256, GSMEM_TOTAL>>>(
      ath, woh, out, nullptr, CM, CM);
}

// round 15
// speedup vs baseline: 1.0888x; 1.0888x over previous
#include <cuda_runtime.h>
#include <cuda_fp16.h>
#include <cstdint>

#define CM 1024
#define TT 2048
#define BB 4
#define HH 16
#define MR (BB*TT)   // 8192 rows

// ---------------------------------------------------------------------------
// Scratch (device globals: allocation-free per harness rules). fp16.
// ---------------------------------------------------------------------------
__device__ __half g_x_hi[(size_t)MR * CM];
__device__ __half g_wqkv_hi[3 * CM * CM];
__device__ __half g_wout_hi[CM * CM];
__device__ __half g_qkv_hi[(size_t)MR * 3 * CM];
__device__ __half g_att_hi[(size_t)MR * CM];

// ---------------------------------------------------------------------------
// helpers
// ---------------------------------------------------------------------------
__device__ __forceinline__ uint32_t smem_u32(const void* p) {
  uint32_t a;
  asm("{ .reg .u64 t; cvta.to.shared.u64 t, %1; cvt.u32.u64 %0, t; }"
      : "=r"(a) : "l"(p));
  return a;
}
__device__ __forceinline__ void cp16(uint32_t s, const void* g) {
  asm volatile("cp.async.cg.shared.global [%0], [%1], 16;" :: "r"(s), "l"(g));
}
#define CP_COMMIT() asm volatile("cp.async.commit_group;" ::: "memory")
#define CP_WAIT(n)  asm volatile("cp.async.wait_group %0;" :: "n"(n) : "memory")

// D += A*B, m16n8k16 fp16 operands, fp32 accumulate
__device__ __forceinline__ void mma16(float* d, uint32_t a0, uint32_t a1,
                                      uint32_t a2, uint32_t a3,
                                      uint32_t b0, uint32_t b1) {
  asm volatile(
      "mma.sync.aligned.m16n8k16.row.col.f32.f16.f16.f32 "
      "{%0,%1,%2,%3}, {%4,%5,%6,%7}, {%8,%9}, {%0,%1,%2,%3};"
      : "+f"(d[0]), "+f"(d[1]), "+f"(d[2]), "+f"(d[3])
      : "r"(a0), "r"(a1), "r"(a2), "r"(a3), "r"(b0), "r"(b1));
}
__device__ __forceinline__ void ldsm4t(uint32_t& r0, uint32_t& r1,
                                       uint32_t& r2, uint32_t& r3, uint32_t a) {
  asm volatile("ldmatrix.sync.aligned.m8n8.x4.trans.shared.b16 "
               "{%0,%1,%2,%3}, [%4];"
               : "=r"(r0), "=r"(r1), "=r"(r2), "=r"(r3) : "r"(a));
}
__device__ __forceinline__ uint32_t ldu(const void* p) {
  return *(const uint32_t*)p;
}
__device__ __forceinline__ uint32_t sw128(uint32_t o) { return o ^ ((o >> 3) & 0x70); }

__device__ __forceinline__ uint32_t pack_h2(float a, float b) {
  __half2 p = __floats2half2_rn(a, b);
  return *(uint32_t*)&p;
}

// ---------------------------------------------------------------------------
// single fused cast kernel: all three fp32 inputs -> fp16
// ---------------------------------------------------------------------------
#define NX (MR * CM / 4)
#define NW (3 * CM * CM / 4)
#define NO (CM * CM / 4)

__global__ __launch_bounds__(256) void cast_all(
    const float* __restrict__ x, const float* __restrict__ wq,
    const float* __restrict__ wo,
    __half* __restrict__ xh, __half* __restrict__ wqh,
    __half* __restrict__ woh) {
  int i = blockIdx.x * blockDim.x + threadIdx.x;
  const float* src;
  __half* dst;
  int j;
  if (i < NX)            { src = x;  dst = xh;  j = i; }
  else if (i < NX + NW)  { src = wq; dst = wqh; j = i - NX; }
  else if (i < NX + NW + NO) { src = wo; dst = woh; j = i - NX - NW; }
  else return;
  float4 v = ((const float4*)src)[j];
  ((uint2*)dst)[j] = make_uint2(pack_h2(v.x, v.y), pack_h2(v.z, v.w));
}

// ---------------------------------------------------------------------------
// fp16 TN GEMM: C[M,N] = Ah[M,K] * Bh[N,K]^T, fp32 accumulate.
// CTA 128x128, BK=128 (KT=8: halves sync/iter overhead vs BK=64), 3-stage
// cp.async, 256 threads (8 warps: 2x4, 64x32 each). Rows are 256B; SW128
// swizzle applied per 128B half. Register double-buffered fragments.
// k-accumulation order identical to BK=64 version (bit-identical output).
// MODE 0: write fp32 C.  MODE 1: write fp16 C.
// ---------------------------------------------------------------------------
#define GSTAGE 65536                    // Ah 32K | Bh 32K
#define GSMEM_TOTAL (3 * GSTAGE)        // 192 KB

template<int MODE>
__global__ __launch_bounds__(256) void gemmH(
    const __half* __restrict__ Ah_, const __half* __restrict__ Bh_,
    float* __restrict__ Cf, __half* __restrict__ Ch, int N, int K) {
  extern __shared__ char sm[];
  const int tid = threadIdx.x, w = tid >> 5, lane = tid & 31;
  const int g = lane >> 2, t = lane & 3;
  const int wm = w & 1, wn = w >> 1;
  const int bm = blockIdx.y * 128, bn = blockIdx.x * 128;

  float acc[4][4][4];
#pragma unroll
  for (int mt = 0; mt < 4; mt++)
#pragma unroll
    for (int nt = 0; nt < 4; nt++)
#pragma unroll
      for (int r = 0; r < 4; r++) acc[mt][nt][r] = 0.f;

  // stage: Ah | Bh, each 128 rows x 256B (128 fp16); swizzle per 128B half
  auto fill = [&](int s, int k0) {
    char* base = sm + s * GSTAGE;
#pragma unroll
    for (int i = tid; i < 4096; i += 256) {
      int buf = i >> 11;            // 0=Ah, 1=Bh  (2048 granules each)
      int row = (i >> 4) & 127;
      int c = i & 15;               // 16B granule within 256B row
      uint32_t swo = (uint32_t)(row * 256 + ((c >> 3) << 7)
                   + ((((uint32_t)(c & 7)) * 16) ^ (((uint32_t)row & 7) << 4)));
      size_t off = (size_t)((buf ? bn : bm) + row) * K + k0 + c * 8;
      cp16(smem_u32(base + buf * 32768 + swo), (buf ? Bh_ : Ah_) + off);
    }
  };

  const int KT = K >> 7;              // 8
  fill(0, 0);    CP_COMMIT();
  fill(1, 128);  CP_COMMIT();
  fill(2, 256);  CP_COMMIT();

  const uint32_t xg = (uint32_t)g << 4;

  for (int c = 0; c < KT; c++) {
    const int s = c - (c / 3) * 3;
    CP_WAIT(2);
    __syncthreads();
    const char* Ah = sm + s * GSTAGE;
    const char* Bh = Ah + 32768;

    uint32_t ah[2][4][4], bh[2][4][2];

    auto loadFrags = [&](int kt, int buf) {
      const uint32_t off = (uint32_t)(kt * 32 + t * 4);
      const uint32_t halfB = (off >> 7) << 7;       // 0 or 128
      const uint32_t xo = (off & 127) ^ xg;
#pragma unroll
      for (int mt = 0; mt < 4; mt++) {
        const char* ar = Ah + (wm * 64 + mt * 16 + g) * 256 + halfB;
        ah[buf][mt][0] = ldu(ar + xo);
        ah[buf][mt][1] = ldu(ar + 2048 + xo);
        ah[buf][mt][2] = ldu(ar + (xo ^ 16));
        ah[buf][mt][3] = ldu(ar + 2048 + (xo ^ 16));
      }
#pragma unroll
      for (int nt = 0; nt < 4; nt++) {
        const char* br = Bh + (wn * 32 + nt * 8 + g) * 256 + halfB;
        bh[buf][nt][0] = ldu(br + xo);
        bh[buf][nt][1] = ldu(br + (xo ^ 16));
      }
    };

    loadFrags(0, 0);
#pragma unroll
    for (int kt = 0; kt < 8; kt++) {
      const int cur = kt & 1;
      if (kt < 7) loadFrags(kt + 1, cur ^ 1);
#pragma unroll
      for (int nt = 0; nt < 4; nt++)
#pragma unroll
        for (int mt = 0; mt < 4; mt++)
          mma16(acc[mt][nt], ah[cur][mt][0], ah[cur][mt][1],
                ah[cur][mt][2], ah[cur][mt][3], bh[cur][nt][0], bh[cur][nt][1]);
    }
    __syncthreads();
    if (c + 3 < KT) fill(s, (c + 3) * 128);
    CP_COMMIT();
  }

#pragma unroll
  for (int mt = 0; mt < 4; mt++) {
#pragma unroll
    for (int nt = 0; nt < 4; nt++) {
      const int row = bm + wm * 64 + mt * 16 + g;
      const int col = bn + wn * 32 + nt * 8 + 2 * t;
      if (MODE == 0) {
        *(float2*)(Cf + (size_t)row * N + col) =
            make_float2(acc[mt][nt][0], acc[mt][nt][1]);
        *(float2*)(Cf + (size_t)(row + 8) * N + col) =
            make_float2(acc[mt][nt][2], acc[mt][nt][3]);
      } else {
        *(uint32_t*)(Ch + (size_t)row * N + col) =
            pack_h2(acc[mt][nt][0], acc[mt][nt][1]);
        *(uint32_t*)(Ch + (size_t)(row + 8) * N + col) =
            pack_h2(acc[mt][nt][2], acc[mt][nt][3]);
      }
    }
  }
}

// ---------------------------------------------------------------------------
// fp16 causal flash attention, 128-query CTA, 4 warps, 2 m16 tiles per warp
// (R12 version verbatim — best measured). S = Qh*Kh^T ; O += Ph*Vh.
// SMEM: Qh 16K | Kh x2 16K | Vh x2 16K = 48KB.
// ---------------------------------------------------------------------------
#define TQ 128
#define AQH 0
#define AKH 16384
#define AVH 32768
#define ASMEM_TOTAL 49152

__global__ __launch_bounds__(128) void attn1(
    const __half* __restrict__ qh, __half* __restrict__ oh) {
  extern __shared__ char sm[];
  const int qi = blockIdx.x, h = blockIdx.y, b = blockIdx.z;
  const int tid = threadIdx.x, w = tid >> 5, lane = tid & 31;
  const int g = lane >> 2, t = lane & 3;
  const int q0 = qi * TQ;
  const size_t rowQ = (size_t)(b * TT + q0);

  auto fillKV = [&](int kb, int bf) {
    const size_t base = (size_t)(b * TT + kb * 64) * 3 * CM + CM + h * 64;
    char* kh = sm + AKH + bf * 8192;
    char* vh = sm + AVH + bf * 8192;
#pragma unroll
    for (int i = tid; i < 512; i += 128) {
      int row = i >> 3, c = i & 7;
      uint32_t swo = sw128((uint32_t)(row * 128 + c * 16));
      size_t src = base + (size_t)row * 3 * CM + c * 8;
      cp16(smem_u32(kh + swo), qh + src);
      cp16(smem_u32(vh + swo), qh + src + CM);
    }
  };

  // prologue: Qh (128 rows) + KV block 0
#pragma unroll
  for (int i = tid; i < 1024; i += 128) {
    int row = i >> 3, c = i & 7;
    uint32_t swo = sw128((uint32_t)(row * 128 + c * 16));
    size_t src = (rowQ + row) * 3 * CM + h * 64 + c * 8;
    cp16(smem_u32(sm + AQH + swo), qh + src);
  }
  fillKV(0, 0);
  CP_COMMIT();

  float m[4] = {-1e30f, -1e30f, -1e30f, -1e30f};   // [tile*2 + rowhalf]
  float l[4] = {0.f, 0.f, 0.f, 0.f};
  float o[2][8][4];
#pragma unroll
  for (int T = 0; T < 2; T++)
#pragma unroll
    for (int j = 0; j < 8; j++)
#pragma unroll
      for (int r = 0; r < 4; r++) o[T][j][r] = 0.f;

  const uint32_t xg = (uint32_t)g << 4;
  const int KJ = 2 * qi + 2;                 // key blocks 0 .. 2qi+1

  for (int kj = 0; kj < KJ; kj++) {
    const int buf = kj & 1;
    if (kj + 1 < KJ) fillKV(kj + 1, buf ^ 1);
    CP_COMMIT();
    CP_WAIT(1);
    __syncthreads();

    const char* Kh = sm + AKH + buf * 8192;
    const char* Qh = sm + AQH;
    const uint32_t vhU = smem_u32(sm + AVH + buf * 8192);

    // ---- S = Qh Kh^T for both tiles (K frags loaded once per kt) ----
    float s[2][8][4];
#pragma unroll
    for (int T = 0; T < 2; T++)
#pragma unroll
      for (int j = 0; j < 8; j++)
#pragma unroll
        for (int r = 0; r < 4; r++) s[T][j][r] = 0.f;

#pragma unroll
    for (int kt = 0; kt < 4; kt++) {
      const uint32_t xo = ((uint32_t)(kt * 32 + t * 4)) ^ xg;
      const char* q0p = Qh + (w * 32 + g) * 128;
      const char* q1p = q0p + 16 * 128;
      uint32_t a00 = ldu(q0p + xo),        a01 = ldu(q0p + 1024 + xo);
      uint32_t a02 = ldu(q0p + (xo ^ 16)), a03 = ldu(q0p + 1024 + (xo ^ 16));
      uint32_t a10 = ldu(q1p + xo),        a11 = ldu(q1p + 1024 + xo);
      uint32_t a12 = ldu(q1p + (xo ^ 16)), a13 = ldu(q1p + 1024 + (xo ^ 16));
#pragma unroll
      for (int j = 0; j < 8; j++) {
        const char* krh = Kh + (j * 8 + g) * 128;
        uint32_t bh0 = ldu(krh + xo), bh1 = ldu(krh + (xo ^ 16));
        mma16(s[0][j], a00, a01, a02, a03, bh0, bh1);
        mma16(s[1][j], a10, a11, a12, a13, bh0, bh1);
      }
    }

    // scale 1/sqrt(64) + causal mask (global-index compare; only near diag)
#pragma unroll
    for (int T = 0; T < 2; T++)
#pragma unroll
      for (int j = 0; j < 8; j++)
#pragma unroll
        for (int r = 0; r < 4; r++) s[T][j][r] *= 0.125f;

    if (kj >= 2 * qi) {
      const int colb = kj * 64;
#pragma unroll
      for (int T = 0; T < 2; T++) {
        const int rg = q0 + w * 32 + T * 16 + g;
#pragma unroll
        for (int j = 0; j < 8; j++) {
          const int c = colb + j * 8 + 2 * t;
          if (c     > rg)     s[T][j][0] = -1e30f;
          if (c + 1 > rg)     s[T][j][1] = -1e30f;
          if (c     > rg + 8) s[T][j][2] = -1e30f;
          if (c + 1 > rg + 8) s[T][j][3] = -1e30f;
        }
      }
    }

    // ---- online softmax per tile ----
    uint32_t ph01[2][8], ph23[2][8];
#pragma unroll
    for (int T = 0; T < 2; T++) {
      float rm0 = -1e30f, rm1 = -1e30f;
#pragma unroll
      for (int j = 0; j < 8; j++) {
        rm0 = fmaxf(rm0, fmaxf(s[T][j][0], s[T][j][1]));
        rm1 = fmaxf(rm1, fmaxf(s[T][j][2], s[T][j][3]));
      }
      rm0 = fmaxf(rm0, __shfl_xor_sync(0xffffffffu, rm0, 1));
      rm0 = fmaxf(rm0, __shfl_xor_sync(0xffffffffu, rm0, 2));
      rm1 = fmaxf(rm1, __shfl_xor_sync(0xffffffffu, rm1, 1));
      rm1 = fmaxf(rm1, __shfl_xor_sync(0xffffffffu, rm1, 2));
      const float mn0 = fmaxf(m[2*T],   rm0);
      const float mn1 = fmaxf(m[2*T+1], rm1);
      const float al0 = __expf(m[2*T]   - mn0);
      const float al1 = __expf(m[2*T+1] - mn1);
      float rs0 = 0.f, rs1 = 0.f;
#pragma unroll
      for (int j = 0; j < 8; j++) {
        s[T][j][0] = __expf(s[T][j][0] - mn0);
        s[T][j][1] = __expf(s[T][j][1] - mn0);
        s[T][j][2] = __expf(s[T][j][2] - mn1);
        s[T][j][3] = __expf(s[T][j][3] - mn1);
        rs0 += s[T][j][0] + s[T][j][1];
        rs1 += s[T][j][2] + s[T][j][3];
      }
      rs0 += __shfl_xor_sync(0xffffffffu, rs0, 1);
      rs0 += __shfl_xor_sync(0xffffffffu, rs0, 2);
      rs1 += __shfl_xor_sync(0xffffffffu, rs1, 1);
      rs1 += __shfl_xor_sync(0xffffffffu, rs1, 2);
      l[2*T]   = l[2*T]   * al0 + rs0;  m[2*T]   = mn0;
      l[2*T+1] = l[2*T+1] * al1 + rs1;  m[2*T+1] = mn1;
#pragma unroll
      for (int j = 0; j < 8; j++) {
        o[T][j][0] *= al0; o[T][j][1] *= al0;
        o[T][j][2] *= al1; o[T][j][3] *= al1;
        ph01[T][j] = pack_h2(s[T][j][0], s[T][j][1]);
        ph23[T][j] = pack_h2(s[T][j][2], s[T][j][3]);
      }
    }

    // ---- O += Ph Vh (V frags loaded once, used by both tiles) ----
    const int qq = lane >> 3, rr = lane & 7;
#pragma unroll
    for (int kt = 0; kt < 4; kt++) {
      const uint32_t p00 = ph01[0][2*kt],   p01 = ph23[0][2*kt];
      const uint32_t p02 = ph01[0][2*kt+1], p03 = ph23[0][2*kt+1];
      const uint32_t p10 = ph01[1][2*kt],   p11 = ph23[1][2*kt];
      const uint32_t p12 = ph01[1][2*kt+1], p13 = ph23[1][2*kt+1];
      const uint32_t vrow = (uint32_t)(kt * 16 + ((qq & 1) << 3) + rr);
#pragma unroll
      for (int jp = 0; jp < 4; jp++) {
        const uint32_t off = sw128(vrow * 128 + (uint32_t)(jp * 32 + ((qq >> 1) << 4)));
        uint32_t vh0, vh1, vh2, vh3;
        ldsm4t(vh0, vh1, vh2, vh3, vhU + off);
        mma16(o[0][2*jp],     p00, p01, p02, p03, vh0, vh1);
        mma16(o[0][2*jp + 1], p00, p01, p02, p03, vh2, vh3);
        mma16(o[1][2*jp],     p10, p11, p12, p13, vh0, vh1);
        mma16(o[1][2*jp + 1], p10, p11, p12, p13, vh2, vh3);
      }
    }
    __syncthreads();   // tiles consumed before next prefetch overwrites
  }

  // ---- epilogue: O /= l, fp16 ----
#pragma unroll
  for (int T = 0; T < 2; T++) {
    const float i0 = 1.f / l[2*T], i1 = 1.f / l[2*T+1];
    const size_t ro0 = (rowQ + w * 32 + T * 16 + g) * CM + h * 64;
    const size_t ro1 = ro0 + 8 * (size_t)CM;
#pragma unroll
    for (int j = 0; j < 8; j++) {
      const int col = j * 8 + 2 * t;
      *(uint32_t*)(oh + ro0 + col) = pack_h2(o[T][j][0] * i0, o[T][j][1] * i0);
      *(uint32_t*)(oh + ro1 + col) = pack_h2(o[T][j][2] * i1, o[T][j][3] * i1);
    }
  }
}

// ---------------------------------------------------------------------------
extern "C" void kernel_launch(void* const* d_in, const int* in_sizes, int n_in,
                              void* d_out, int out_size) {
  const float* x     = (const float*)d_in[0];   // [4,2048,1024]
  const float* w_qkv = (const float*)d_in[1];   // [3072,1024]
  const float* w_out = (const float*)d_in[2];   // [1024,1024]
  float* out = (float*)d_out;

  __half *xh, *wqh, *woh, *qkvh, *ath;
  cudaGetSymbolAddress((void**)&xh,  g_x_hi);
  cudaGetSymbolAddress((void**)&wqh, g_wqkv_hi);
  cudaGetSymbolAddress((void**)&woh, g_wout_hi);
  cudaGetSymbolAddress((void**)&qkvh, g_qkv_hi);
  cudaGetSymbolAddress((void**)&ath, g_att_hi);

  cudaFuncSetAttribute(gemmH<1>, cudaFuncAttributeMaxDynamicSharedMemorySize, GSMEM_TOTAL);
  cudaFuncSetAttribute(gemmH<0>, cudaFuncAttributeMaxDynamicSharedMemorySize, GSMEM_TOTAL);
  cudaFuncSetAttribute(attn1,    cudaFuncAttributeMaxDynamicSharedMemorySize, ASMEM_TOTAL);

  // 0) cast all inputs to fp16 (single launch)
  cast_all<<<(NX + NW + NO + 255) / 256, 256>>>(x, w_qkv, w_out, xh, wqh, woh);

  // 1) QKV projection -> qkv fp16 (1-pass)
  gemmH<1><<<dim3(3*CM/128, MR/128), 256, GSMEM_TOTAL>>>(
      xh, wqh, nullptr, qkvh, 3*CM, CM);

  // 2) causal flash attention -> att fp16 (TQ=128, 4 warps, 2 tiles/warp)
  attn1<<<dim3(TT/TQ, HH, BB), 128, ASMEM_TOTAL>>>(qkvh, ath);

  // 3) output projection -> fp32 out (1-pass)
  gemmH<0><<<dim3(CM/128, MR/128), 256, GSMEM_TOTAL>>>(
      ath, woh, out, nullptr, CM, CM);
}

// round 17
// speedup vs baseline: 1.0900x; 1.0011x over previous
#include <cuda_runtime.h>
#include <cuda_fp16.h>
#include <cstdint>

#define CM 1024
#define TT 2048
#define BB 4
#define HH 16
#define MR (BB*TT)   // 8192 rows

// ---------------------------------------------------------------------------
// Scratch (device globals: allocation-free per harness rules). fp16.
// ---------------------------------------------------------------------------
__device__ __half g_x_hi[(size_t)MR * CM];
__device__ __half g_wqkv_hi[3 * CM * CM];
__device__ __half g_wout_hi[CM * CM];
__device__ __half g_qkv_hi[(size_t)MR * 3 * CM];
__device__ __half g_att_hi[(size_t)MR * CM];

// ---------------------------------------------------------------------------
// helpers
// ---------------------------------------------------------------------------
__device__ __forceinline__ uint32_t smem_u32(const void* p) {
  uint32_t a;
  asm("{ .reg .u64 t; cvta.to.shared.u64 t, %1; cvt.u32.u64 %0, t; }"
      : "=r"(a) : "l"(p));
  return a;
}
__device__ __forceinline__ void cp16(uint32_t s, const void* g) {
  asm volatile("cp.async.cg.shared.global [%0], [%1], 16;" :: "r"(s), "l"(g));
}
#define CP_COMMIT() asm volatile("cp.async.commit_group;" ::: "memory")
#define CP_WAIT(n)  asm volatile("cp.async.wait_group %0;" :: "n"(n) : "memory")

// D += A*B, m16n8k16 fp16 operands, fp32 accumulate
__device__ __forceinline__ void mma16(float* d, uint32_t a0, uint32_t a1,
                                      uint32_t a2, uint32_t a3,
                                      uint32_t b0, uint32_t b1) {
  asm volatile(
      "mma.sync.aligned.m16n8k16.row.col.f32.f16.f16.f32 "
      "{%0,%1,%2,%3}, {%4,%5,%6,%7}, {%8,%9}, {%0,%1,%2,%3};"
      : "+f"(d[0]), "+f"(d[1]), "+f"(d[2]), "+f"(d[3])
      : "r"(a0), "r"(a1), "r"(a2), "r"(a3), "r"(b0), "r"(b1));
}
__device__ __forceinline__ void ldsm4t(uint32_t& r0, uint32_t& r1,
                                       uint32_t& r2, uint32_t& r3, uint32_t a) {
  asm volatile("ldmatrix.sync.aligned.m8n8.x4.trans.shared.b16 "
               "{%0,%1,%2,%3}, [%4];"
               : "=r"(r0), "=r"(r1), "=r"(r2), "=r"(r3) : "r"(a));
}
__device__ __forceinline__ uint32_t ldu(const void* p) {
  return *(const uint32_t*)p;
}
__device__ __forceinline__ uint32_t sw128(uint32_t o) { return o ^ ((o >> 3) & 0x70); }

__device__ __forceinline__ uint32_t pack_h2(float a, float b) {
  __half2 p = __floats2half2_rn(a, b);
  return *(uint32_t*)&p;
}

// ---------------------------------------------------------------------------
// single fused cast kernel: all three fp32 inputs -> fp16
// ---------------------------------------------------------------------------
#define NX (MR * CM / 4)
#define NW (3 * CM * CM / 4)
#define NO (CM * CM / 4)

__global__ __launch_bounds__(256) void cast_all(
    const float* __restrict__ x, const float* __restrict__ wq,
    const float* __restrict__ wo,
    __half* __restrict__ xh, __half* __restrict__ wqh,
    __half* __restrict__ woh) {
  int i = blockIdx.x * blockDim.x + threadIdx.x;
  const float* src;
  __half* dst;
  int j;
  if (i < NX)            { src = x;  dst = xh;  j = i; }
  else if (i < NX + NW)  { src = wq; dst = wqh; j = i - NX; }
  else if (i < NX + NW + NO) { src = wo; dst = woh; j = i - NX - NW; }
  else return;
  float4 v = ((const float4*)src)[j];
  ((uint2*)dst)[j] = make_uint2(pack_h2(v.x, v.y), pack_h2(v.z, v.w));
}

// ---------------------------------------------------------------------------
// fp16 TN GEMM: C[M,N] = Ah[M,K] * Bh[N,K]^T, fp32 accumulate.
// CTA 128x128, BK=128 (KT=8), 3-stage cp.async, 256 threads (R15, best).
// MODE 0: write fp32 C.  MODE 1: write fp16 C.
// ---------------------------------------------------------------------------
#define GSTAGE 65536                    // Ah 32K | Bh 32K
#define GSMEM_TOTAL (3 * GSTAGE)        // 192 KB

template<int MODE>
__global__ __launch_bounds__(256) void gemmH(
    const __half* __restrict__ Ah_, const __half* __restrict__ Bh_,
    float* __restrict__ Cf, __half* __restrict__ Ch, int N, int K) {
  extern __shared__ char sm[];
  const int tid = threadIdx.x, w = tid >> 5, lane = tid & 31;
  const int g = lane >> 2, t = lane & 3;
  const int wm = w & 1, wn = w >> 1;
  const int bm = blockIdx.y * 128, bn = blockIdx.x * 128;

  float acc[4][4][4];
#pragma unroll
  for (int mt = 0; mt < 4; mt++)
#pragma unroll
    for (int nt = 0; nt < 4; nt++)
#pragma unroll
      for (int r = 0; r < 4; r++) acc[mt][nt][r] = 0.f;

  // stage: Ah | Bh, each 128 rows x 256B (128 fp16); swizzle per 128B half
  auto fill = [&](int s, int k0) {
    char* base = sm + s * GSTAGE;
#pragma unroll
    for (int i = tid; i < 4096; i += 256) {
      int buf = i >> 11;            // 0=Ah, 1=Bh  (2048 granules each)
      int row = (i >> 4) & 127;
      int c = i & 15;               // 16B granule within 256B row
      uint32_t swo = (uint32_t)(row * 256 + ((c >> 3) << 7)
                   + ((((uint32_t)(c & 7)) * 16) ^ (((uint32_t)row & 7) << 4)));
      size_t off = (size_t)((buf ? bn : bm) + row) * K + k0 + c * 8;
      cp16(smem_u32(base + buf * 32768 + swo), (buf ? Bh_ : Ah_) + off);
    }
  };

  const int KT = K >> 7;              // 8
  fill(0, 0);    CP_COMMIT();
  fill(1, 128);  CP_COMMIT();
  fill(2, 256);  CP_COMMIT();

  const uint32_t xg = (uint32_t)g << 4;

  for (int c = 0; c < KT; c++) {
    const int s = c - (c / 3) * 3;
    CP_WAIT(2);
    __syncthreads();
    const char* Ah = sm + s * GSTAGE;
    const char* Bh = Ah + 32768;

    uint32_t ah[2][4][4], bh[2][4][2];

    auto loadFrags = [&](int kt, int buf) {
      const uint32_t off = (uint32_t)(kt * 32 + t * 4);
      const uint32_t halfB = (off >> 7) << 7;       // 0 or 128
      const uint32_t xo = (off & 127) ^ xg;
#pragma unroll
      for (int mt = 0; mt < 4; mt++) {
        const char* ar = Ah + (wm * 64 + mt * 16 + g) * 256 + halfB;
        ah[buf][mt][0] = ldu(ar + xo);
        ah[buf][mt][1] = ldu(ar + 2048 + xo);
        ah[buf][mt][2] = ldu(ar + (xo ^ 16));
        ah[buf][mt][3] = ldu(ar + 2048 + (xo ^ 16));
      }
#pragma unroll
      for (int nt = 0; nt < 4; nt++) {
        const char* br = Bh + (wn * 32 + nt * 8 + g) * 256 + halfB;
        bh[buf][nt][0] = ldu(br + xo);
        bh[buf][nt][1] = ldu(br + (xo ^ 16));
      }
    };

    loadFrags(0, 0);
#pragma unroll
    for (int kt = 0; kt < 8; kt++) {
      const int cur = kt & 1;
      if (kt < 7) loadFrags(kt + 1, cur ^ 1);
#pragma unroll
      for (int nt = 0; nt < 4; nt++)
#pragma unroll
        for (int mt = 0; mt < 4; mt++)
          mma16(acc[mt][nt], ah[cur][mt][0], ah[cur][mt][1],
                ah[cur][mt][2], ah[cur][mt][3], bh[cur][nt][0], bh[cur][nt][1]);
    }
    __syncthreads();
    if (c + 3 < KT) fill(s, (c + 3) * 128);
    CP_COMMIT();
  }

#pragma unroll
  for (int mt = 0; mt < 4; mt++) {
#pragma unroll
    for (int nt = 0; nt < 4; nt++) {
      const int row = bm + wm * 64 + mt * 16 + g;
      const int col = bn + wn * 32 + nt * 8 + 2 * t;
      if (MODE == 0) {
        *(float2*)(Cf + (size_t)row * N + col) =
            make_float2(acc[mt][nt][0], acc[mt][nt][1]);
        *(float2*)(Cf + (size_t)(row + 8) * N + col) =
            make_float2(acc[mt][nt][2], acc[mt][nt][3]);
      } else {
        *(uint32_t*)(Ch + (size_t)row * N + col) =
            pack_h2(acc[mt][nt][0], acc[mt][nt][1]);
        *(uint32_t*)(Ch + (size_t)(row + 8) * N + col) =
            pack_h2(acc[mt][nt][2], acc[mt][nt][3]);
      }
    }
  }
}

// ---------------------------------------------------------------------------
// fp16 causal flash attention, 128-query CTA, 4 warps, 2 m16 tiles per warp.
// Single sync per kj with CORRECT ordering: WAIT -> sync -> fill -> read
// (sync after per-thread wait makes all threads' cp.async data visible;
// refill slot (kj+2)%3 was last read at kj-1, protected by this sync).
// LJF dispatch: heavy (high-qi) blocks first.
// SMEM: Qh 16K | Kh x3 24K | Vh x3 24K = 64KB.
// ---------------------------------------------------------------------------
#define TQ 128
#define AQH 0
#define AKH 16384
#define AVH 40960
#define ASMEM_TOTAL 65536

__global__ __launch_bounds__(128) void attn1(
    const __half* __restrict__ qh, __half* __restrict__ oh) {
  extern __shared__ char sm[];
  const int qi = (TT / TQ - 1) - blockIdx.x;   // heavy blocks first
  const int h = blockIdx.y, b = blockIdx.z;
  const int tid = threadIdx.x, w = tid >> 5, lane = tid & 31;
  const int g = lane >> 2, t = lane & 3;
  const int q0 = qi * TQ;
  const size_t rowQ = (size_t)(b * TT + q0);

  auto fillKV = [&](int kb, int slot) {
    const size_t base = (size_t)(b * TT + kb * 64) * 3 * CM + CM + h * 64;
    char* kh = sm + AKH + slot * 8192;
    char* vh = sm + AVH + slot * 8192;
#pragma unroll
    for (int i = tid; i < 512; i += 128) {
      int row = i >> 3, c = i & 7;
      uint32_t swo = sw128((uint32_t)(row * 128 + c * 16));
      size_t src = base + (size_t)row * 3 * CM + c * 8;
      cp16(smem_u32(kh + swo), qh + src);
      cp16(smem_u32(vh + swo), qh + src + CM);
    }
  };

  // prologue: Qh (128 rows) + KV blocks 0,1  (KJ >= 2 always)
#pragma unroll
  for (int i = tid; i < 1024; i += 128) {
    int row = i >> 3, c = i & 7;
    uint32_t swo = sw128((uint32_t)(row * 128 + c * 16));
    size_t src = (rowQ + row) * 3 * CM + h * 64 + c * 8;
    cp16(smem_u32(sm + AQH + swo), qh + src);
  }
  fillKV(0, 0);
  CP_COMMIT();        // G0: Q + block0
  fillKV(1, 1);
  CP_COMMIT();        // G1: block1

  float m[4] = {-1e30f, -1e30f, -1e30f, -1e30f};   // [tile*2 + rowhalf]
  float l[4] = {0.f, 0.f, 0.f, 0.f};
  float o[2][8][4];
#pragma unroll
  for (int T = 0; T < 2; T++)
#pragma unroll
    for (int j = 0; j < 8; j++)
#pragma unroll
      for (int r = 0; r < 4; r++) o[T][j][r] = 0.f;

  const uint32_t xg = (uint32_t)g << 4;
  const int KJ = 2 * qi + 2;                 // key blocks 0 .. 2qi+1

  int slc = 0;   // slot of current kj
  int slf = 2;   // slot of kj+2 (prefetch target)

  for (int kj = 0; kj < KJ; kj++) {
    CP_WAIT(1);        // my groups through G_kj complete (G_{kj+1} may fly)
    __syncthreads();   // ALL threads' waits done -> data visible; slot slf free
    if (kj + 2 < KJ) fillKV(kj + 2, slf);
    CP_COMMIT();       // unconditional: keeps group count aligned

    const char* Kh = sm + AKH + slc * 8192;
    const char* Qh = sm + AQH;
    const uint32_t vhU = smem_u32(sm + AVH + slc * 8192);
    slc = (slc == 2) ? 0 : slc + 1;
    slf = (slf == 2) ? 0 : slf + 1;

    // ---- S = Qh Kh^T for both tiles (K frags loaded once per kt) ----
    float s[2][8][4];
#pragma unroll
    for (int T = 0; T < 2; T++)
#pragma unroll
      for (int j = 0; j < 8; j++)
#pragma unroll
        for (int r = 0; r < 4; r++) s[T][j][r] = 0.f;

#pragma unroll
    for (int kt = 0; kt < 4; kt++) {
      const uint32_t xo = ((uint32_t)(kt * 32 + t * 4)) ^ xg;
      const char* q0p = Qh + (w * 32 + g) * 128;
      const char* q1p = q0p + 16 * 128;
      uint32_t a00 = ldu(q0p + xo),        a01 = ldu(q0p + 1024 + xo);
      uint32_t a02 = ldu(q0p + (xo ^ 16)), a03 = ldu(q0p + 1024 + (xo ^ 16));
      uint32_t a10 = ldu(q1p + xo),        a11 = ldu(q1p + 1024 + xo);
      uint32_t a12 = ldu(q1p + (xo ^ 16)), a13 = ldu(q1p + 1024 + (xo ^ 16));
#pragma unroll
      for (int j = 0; j < 8; j++) {
        const char* krh = Kh + (j * 8 + g) * 128;
        uint32_t bh0 = ldu(krh + xo), bh1 = ldu(krh + (xo ^ 16));
        mma16(s[0][j], a00, a01, a02, a03, bh0, bh1);
        mma16(s[1][j], a10, a11, a12, a13, bh0, bh1);
      }
    }

    // scale 1/sqrt(64) + causal mask (global-index compare; only near diag)
#pragma unroll
    for (int T = 0; T < 2; T++)
#pragma unroll
      for (int j = 0; j < 8; j++)
#pragma unroll
        for (int r = 0; r < 4; r++) s[T][j][r] *= 0.125f;

    if (kj >= 2 * qi) {
      const int colb = kj * 64;
#pragma unroll
      for (int T = 0; T < 2; T++) {
        const int rg = q0 + w * 32 + T * 16 + g;
#pragma unroll
        for (int j = 0; j < 8; j++) {
          const int c = colb + j * 8 + 2 * t;
          if (c     > rg)     s[T][j][0] = -1e30f;
          if (c + 1 > rg)     s[T][j][1] = -1e30f;
          if (c     > rg + 8) s[T][j][2] = -1e30f;
          if (c + 1 > rg + 8) s[T][j][3] = -1e30f;
        }
      }
    }

    // ---- online softmax per tile ----
    uint32_t ph01[2][8], ph23[2][8];
#pragma unroll
    for (int T = 0; T < 2; T++) {
      float rm0 = -1e30f, rm1 = -1e30f;
#pragma unroll
      for (int j = 0; j < 8; j++) {
        rm0 = fmaxf(rm0, fmaxf(s[T][j][0], s[T][j][1]));
        rm1 = fmaxf(rm1, fmaxf(s[T][j][2], s[T][j][3]));
      }
      rm0 = fmaxf(rm0, __shfl_xor_sync(0xffffffffu, rm0, 1));
      rm0 = fmaxf(rm0, __shfl_xor_sync(0xffffffffu, rm0, 2));
      rm1 = fmaxf(rm1, __shfl_xor_sync(0xffffffffu, rm1, 1));
      rm1 = fmaxf(rm1, __shfl_xor_sync(0xffffffffu, rm1, 2));
      const float mn0 = fmaxf(m[2*T],   rm0);
      const float mn1 = fmaxf(m[2*T+1], rm1);
      const float al0 = __expf(m[2*T]   - mn0);
      const float al1 = __expf(m[2*T+1] - mn1);
      float rs0 = 0.f, rs1 = 0.f;
#pragma unroll
      for (int j = 0; j < 8; j++) {
        s[T][j][0] = __expf(s[T][j][0] - mn0);
        s[T][j][1] = __expf(s[T][j][1] - mn0);
        s[T][j][2] = __expf(s[T][j][2] - mn1);
        s[T][j][3] = __expf(s[T][j][3] - mn1);
        rs0 += s[T][j][0] + s[T][j][1];
        rs1 += s[T][j][2] + s[T][j][3];
      }
      rs0 += __shfl_xor_sync(0xffffffffu, rs0, 1);
      rs0 += __shfl_xor_sync(0xffffffffu, rs0, 2);
      rs1 += __shfl_xor_sync(0xffffffffu, rs1, 1);
      rs1 += __shfl_xor_sync(0xffffffffu, rs1, 2);
      l[2*T]   = l[2*T]   * al0 + rs0;  m[2*T]   = mn0;
      l[2*T+1] = l[2*T+1] * al1 + rs1;  m[2*T+1] = mn1;
#pragma unroll
      for (int j = 0; j < 8; j++) {
        o[T][j][0] *= al0; o[T][j][1] *= al0;
        o[T][j][2] *= al1; o[T][j][3] *= al1;
        ph01[T][j] = pack_h2(s[T][j][0], s[T][j][1]);
        ph23[T][j] = pack_h2(s[T][j][2], s[T][j][3]);
      }
    }

    // ---- O += Ph Vh (V frags loaded once, used by both tiles) ----
    const int qq = lane >> 3, rr = lane & 7;
#pragma unroll
    for (int kt = 0; kt < 4; kt++) {
      const uint32_t p00 = ph01[0][2*kt],   p01 = ph23[0][2*kt];
      const uint32_t p02 = ph01[0][2*kt+1], p03 = ph23[0][2*kt+1];
      const uint32_t p10 = ph01[1][2*kt],   p11 = ph23[1][2*kt];
      const uint32_t p12 = ph01[1][2*kt+1], p13 = ph23[1][2*kt+1];
      const uint32_t vrow = (uint32_t)(kt * 16 + ((qq & 1) << 3) + rr);
#pragma unroll
      for (int jp = 0; jp < 4; jp++) {
        const uint32_t off = sw128(vrow * 128 + (uint32_t)(jp * 32 + ((qq >> 1) << 4)));
        uint32_t vh0, vh1, vh2, vh3;
        ldsm4t(vh0, vh1, vh2, vh3, vhU + off);
        mma16(o[0][2*jp],     p00, p01, p02, p03, vh0, vh1);
        mma16(o[0][2*jp + 1], p00, p01, p02, p03, vh2, vh3);
        mma16(o[1][2*jp],     p10, p11, p12, p13, vh0, vh1);
        mma16(o[1][2*jp + 1], p10, p11, p12, p13, vh2, vh3);
      }
    }
  }

  // ---- epilogue: O /= l, fp16 ----
#pragma unroll
  for (int T = 0; T < 2; T++) {
    const float i0 = 1.f / l[2*T], i1 = 1.f / l[2*T+1];
    const size_t ro0 = (rowQ + w * 32 + T * 16 + g) * CM + h * 64;
    const size_t ro1 = ro0 + 8 * (size_t)CM;
#pragma unroll
    for (int j = 0; j < 8; j++) {
      const int col = j * 8 + 2 * t;
      *(uint32_t*)(oh + ro0 + col) = pack_h2(o[T][j][0] * i0, o[T][j][1] * i0);
      *(uint32_t*)(oh + ro1 + col) = pack_h2(o[T][j][2] * i1, o[T][j][3] * i1);
    }
  }
}

// ---------------------------------------------------------------------------
extern "C" void kernel_launch(void* const* d_in, const int* in_sizes, int n_in,
                              void* d_out, int out_size) {
  const float* x     = (const float*)d_in[0];   // [4,2048,1024]
  const float* w_qkv = (const float*)d_in[1];   // [3072,1024]
  const float* w_out = (const float*)d_in[2];   // [1024,1024]
  float* out = (float*)d_out;

  __half *xh, *wqh, *woh, *qkvh, *ath;
  cudaGetSymbolAddress((void**)&xh,  g_x_hi);
  cudaGetSymbolAddress((void**)&wqh, g_wqkv_hi);
  cudaGetSymbolAddress((void**)&woh, g_wout_hi);
  cudaGetSymbolAddress((void**)&qkvh, g_qkv_hi);
  cudaGetSymbolAddress((void**)&ath, g_att_hi);

  cudaFuncSetAttribute(gemmH<1>, cudaFuncAttributeMaxDynamicSharedMemorySize, GSMEM_TOTAL);
  cudaFuncSetAttribute(gemmH<0>, cudaFuncAttributeMaxDynamicSharedMemorySize, GSMEM_TOTAL);
  cudaFuncSetAttribute(attn1,    cudaFuncAttributeMaxDynamicSharedMemorySize, ASMEM_TOTAL);

  // 0) cast all inputs to fp16 (single launch)
  cast_all<<<(NX + NW + NO + 255) / 256, 256>>>(x, w_qkv, w_out, xh, wqh, woh);

  // 1) QKV projection -> qkv fp16 (1-pass)
  gemmH<1><<<dim3(3*CM/128, MR/128), 256, GSMEM_TOTAL>>>(
      xh, wqh, nullptr, qkvh, 3*CM, CM);

  // 2) causal flash attention -> att fp16 (TQ=128, LJF, 3-slot single-sync)
  attn1<<<dim3(TT/TQ, HH, BB), 128, ASMEM_TOTAL>>>(qkvh, ath);

  // 3) output projection -> fp32 out (1-pass)
  gemmH<0><<<dim3(CM/128, MR/128), 256, GSMEM_TOTAL>>>(
      ath, woh, out, nullptr, CM, CM);
}